// round 9
// baseline (speedup 1.0000x reference)
#include <cuda_runtime.h>
#include <cuda_bf16.h>

// ROI align 2.5D — separable-weight formulation, two-kernel pipeline.
// fea: (B=16, C=64, H=128, W=128, D=8) f32. keypoints: (16,5,3) f32.
// out: (16, 5, 64, 2, 2, 8) f32.
//
// Per (ROI, bin): out[c,d] = (1/(gh*gw)) * sum_y Wy[y] * sum_x Wx[x] * fea[b,c,y,x,d]
//
// R9: kernel 1 precomputes per-(ROI,bin) axis weight vectors + metadata into
// __device__ scratch. Kernel 2 (hot) has NO shared mem, NO __syncthreads, no
// serial prologue: warps read broadcast weights (L1/L2-hot) and stream DRAM
// loads immediately. Each warp handles 2 channels (4 LDG.128 streams/iter).

#define RB  16
#define RC  64
#define RH  128
#define RW  128
#define RD  8
#define NKP 5
#define NROI (RB * NKP)          // 80
#define NRB  (NROI * 4)          // ROI x bin work items = 320
#define CROP 16.0f               // H * 1/8
#define WSLOTS 32                // zero-padded so Wx[x+16] is always in-bounds
#define WPB 8                    // warps per block

// Scratch: weights + metadata per (ROI, bin).
__device__ float g_W[NRB][2][WSLOTS];      // [rb][axis][slot], axis0=x, axis1=y
__device__ int   g_meta[NRB][8];           // x0,y0,nx,ny,gw,gh

__global__ void roi_weights_kernel(const float* __restrict__ kp) {
    const int tid = blockIdx.x * blockDim.x + threadIdx.x;
    if (tid >= NRB * 2) return;
    const int axis = tid & 1;                // 0=x, 1=y
    const int rb   = tid >> 1;
    const int bin  = rb & 3;
    const int n    = rb >> 2;
    const int ph   = bin >> 1;
    const int pw   = bin & 1;

    float coord = kp[n * 3 + axis] * 128.0f;
    float mn = fminf(fmaxf(coord - CROP, 0.0f), 127.0f);
    float mx = fminf(fmaxf(coord + CROP, 0.0f), 127.0f);
    float roi = fmaxf(mx - mn, 1.0f);
    float bin_sz = roi * 0.5f;               // roi / P (P=2)
    int   g = (int)ceilf(bin_sz);            // ceil(roi/2), 1..16
    float step = bin_sz / (float)g;
    int   p = (axis == 0) ? pw : ph;
    float start = mn + (float)p * bin_sz;

    float W[WSLOTS];
    #pragma unroll
    for (int i = 0; i < WSLOTS; i++) W[i] = 0.0f;

    float s0 = start + 0.5f * step;
    int base = (int)floorf(fmaxf(s0, 0.0f));
    if (base > 127) base = 127;
    int maxc = base;

    for (int gi = 0; gi < g; gi++) {
        float s = start + ((float)gi + 0.5f) * step;
        if (s < -1.0f || s > 128.0f) continue;       // validity mask
        float c0 = fmaxf(s, 0.0f);
        int l0 = (int)floorf(c0);
        int lo, hi; float fr;
        if (l0 >= 127) { lo = 127; hi = 127; fr = 0.0f; }
        else           { lo = l0;  hi = l0 + 1; fr = c0 - (float)l0; }
        W[lo - base] += 1.0f - fr;
        W[hi - base] += fr;
        if (hi > maxc) maxc = hi;
    }

    #pragma unroll
    for (int i = 0; i < WSLOTS; i++) g_W[rb][axis][i] = W[i];
    g_meta[rb][axis]     = base;             // x0 / y0
    g_meta[rb][2 + axis] = maxc - base + 1;  // nx / ny
    g_meta[rb][4 + axis] = g;                // gw / gh
}

__global__ __launch_bounds__(256)
void roi_align_25d_kernel(const float* __restrict__ fea,
                          float* __restrict__ out) {
    const int blk = blockIdx.x;          // 1280 blocks: ROI x bin x cg
    const int cg  = blk & 3;             // channel group (16 ch)
    const int bin = (blk >> 2) & 3;      // ph*2 + pw
    const int n   = blk >> 4;            // ROI index 0..79
    const int rb  = (n << 2) | bin;
    const int ph  = bin >> 1;
    const int pw  = bin & 1;
    const int b   = n / NKP;

    const int t    = threadIdx.x;
    const int wid  = t >> 5;
    const int lane = t & 31;
    const int x    = lane >> 1;          // x-pixel within window, 0..15
    const int dq   = lane & 1;           // which float4 of the 8-float depth

    // Broadcast metadata loads (uniform per block, L1/L2-hot).
    const int x0 = g_meta[rb][0];
    const int y0 = g_meta[rb][1];
    const int nx = g_meta[rb][2];
    const int ny = g_meta[rb][3];
    const float inv = 1.0f / ((float)(g_meta[rb][4] * g_meta[rb][5]));

    const float* __restrict__ Wx = g_W[rb][0];
    const float* __restrict__ Wy = g_W[rb][1];

    const int cA = cg * 16 + wid;        // first channel of this warp
    // second channel = cA + 8

    const float4* __restrict__ fp = (const float4*)fea;

    const float wx1 = __ldg(&Wx[x]);
    const float wx2 = __ldg(&Wx[x + 16]);        // zero-padded -> safe
    const int   xe1 = (x < nx) ? x : 0;          // clamp OOW lanes (weight 0)
    const bool  tail = (x + 16 < nx);

    // float4 index: (((b*C + c)*H + y)*W + x)*2 + dq   (max ~33.5M, fits int)
    const int rowStride = RW * 2;
    const int chStride8 = 8 * RH * RW * 2;       // +8 channels, in float4s
    const int idxA1 = (((b * RC + cA) * RH + y0) * RW + x0 + xe1) * 2 + dq;
    const int idxA2 = idxA1 + 32;                // x + 16
    const int idxB1 = idxA1 + chStride8;
    const int idxB2 = idxB1 + 32;

    float4 a1 = make_float4(0.f, 0.f, 0.f, 0.f);
    float4 a2 = make_float4(0.f, 0.f, 0.f, 0.f);
    float4 b1 = make_float4(0.f, 0.f, 0.f, 0.f);
    float4 b2 = make_float4(0.f, 0.f, 0.f, 0.f);

    if (nx <= 16) {
        #pragma unroll 4
        for (int iy = 0; iy < ny; iy++) {
            const float wy = __ldg(&Wy[iy]);
            const float4 va = fp[idxA1 + iy * rowStride];
            const float4 vb = fp[idxB1 + iy * rowStride];
            a1.x += wy * va.x;  a1.y += wy * va.y;
            a1.z += wy * va.z;  a1.w += wy * va.w;
            b1.x += wy * vb.x;  b1.y += wy * vb.y;
            b1.z += wy * vb.z;  b1.w += wy * vb.w;
        }
    } else {
        #pragma unroll 2
        for (int iy = 0; iy < ny; iy++) {
            const float wy = __ldg(&Wy[iy]);
            const float4 va1 = fp[idxA1 + iy * rowStride];
            const float4 vb1 = fp[idxB1 + iy * rowStride];
            float4 va2 = make_float4(0.f, 0.f, 0.f, 0.f);
            float4 vb2 = make_float4(0.f, 0.f, 0.f, 0.f);
            if (tail) {
                va2 = fp[idxA2 + iy * rowStride];
                vb2 = fp[idxB2 + iy * rowStride];
            }
            a1.x += wy * va1.x;  a1.y += wy * va1.y;
            a1.z += wy * va1.z;  a1.w += wy * va1.w;
            b1.x += wy * vb1.x;  b1.y += wy * vb1.y;
            b1.z += wy * vb1.z;  b1.w += wy * vb1.w;
            a2.x += wy * va2.x;  a2.y += wy * va2.y;
            a2.z += wy * va2.z;  a2.w += wy * va2.w;
            b2.x += wy * vb2.x;  b2.y += wy * vb2.y;
            b2.z += wy * vb2.z;  b2.w += wy * vb2.w;
        }
    }

    float4 sa, sb;
    sa.x = wx1 * a1.x + wx2 * a2.x;  sa.y = wx1 * a1.y + wx2 * a2.y;
    sa.z = wx1 * a1.z + wx2 * a2.z;  sa.w = wx1 * a1.w + wx2 * a2.w;
    sb.x = wx1 * b1.x + wx2 * b2.x;  sb.y = wx1 * b1.y + wx2 * b2.y;
    sb.z = wx1 * b1.z + wx2 * b2.z;  sb.w = wx1 * b1.w + wx2 * b2.w;

    // Reduce over x (lane bits 1..4); every lane ends with the total for its dq.
    #pragma unroll
    for (int m = 2; m <= 16; m <<= 1) {
        sa.x += __shfl_xor_sync(0xffffffffu, sa.x, m);
        sa.y += __shfl_xor_sync(0xffffffffu, sa.y, m);
        sa.z += __shfl_xor_sync(0xffffffffu, sa.z, m);
        sa.w += __shfl_xor_sync(0xffffffffu, sa.w, m);
        sb.x += __shfl_xor_sync(0xffffffffu, sb.x, m);
        sb.y += __shfl_xor_sync(0xffffffffu, sb.y, m);
        sb.z += __shfl_xor_sync(0xffffffffu, sb.z, m);
        sb.w += __shfl_xor_sync(0xffffffffu, sb.w, m);
    }

    // out: (NROI, C, 2, 2, 8) -> float4 index (((n*C+c)*2+ph)*2+pw)*2+dq
    float4* __restrict__ op = (float4*)out;
    if (lane < 2) {
        float4 s = sa;
        s.x *= inv; s.y *= inv; s.z *= inv; s.w *= inv;
        op[(((n * RC + cA) * 2 + ph) * 2 + pw) * 2 + dq] = s;
    } else if (lane < 4) {
        float4 s = sb;          // lanes 2,3 carry dq 0,1 for channel cA+8
        s.x *= inv; s.y *= inv; s.z *= inv; s.w *= inv;
        op[(((n * RC + cA + 8) * 2 + ph) * 2 + pw) * 2 + dq] = s;
    }
}

extern "C" void kernel_launch(void* const* d_in, const int* in_sizes, int n_in,
                              void* d_out, int out_size) {
    const float* fea = (const float*)d_in[0];
    const float* kp  = (const float*)d_in[1];
    float* out = (float*)d_out;
    (void)in_sizes; (void)n_in; (void)out_size;

    roi_weights_kernel<<<(NRB * 2 + 127) / 128, 128>>>(kp);

    dim3 grid(NROI * 4 * 4);   // 1280 blocks: ROI x bin x channel-group(16)
    dim3 block(32 * WPB);      // 8 warps, each: 2 channels x 16 x-px x 2 dq
    roi_align_25d_kernel<<<grid, block>>>(fea, out);
}

// round 10
// speedup vs baseline: 1.1019x; 1.1019x over previous
#include <cuda_runtime.h>
#include <cuda_bf16.h>

// ROI align 2.5D — separable weights + 4-bin union fusion.
// fea: (B=16, C=64, H=128, W=128, D=8) f32. keypoints: (16,5,3) f32.
// out: (16, 5, 64, 2, 2, 8) f32.
//
// out[n,c,ph,pw,d] = (1/(gh*gw)) * sum_y Wy[ph][y] * sum_x Wx[pw][x] * fea[b,c,y,x,d]
//
// R10: one block = (ROI, 4-channel group). Each warp owns one channel and
// sweeps the UNION window of all four bins: each union row (~34 px = ~1088B)
// is read ONCE as contiguous spans and reused for all 4 (ph,pw) bins via
// per-axis weight vectors. Doubles DRAM span length (row-buffer locality),
// halves LDG count vs per-bin kernels.

#define RB  16
#define RC  64
#define RH  128
#define RW  128
#define NKP 5
#define NROI (RB * NKP)          // 80
#define CROP 16.0f               // H * 1/8
#define WSLOTS 64                // union slots (<=34 used), zero-padded
#define WPB 4                    // warps (channels) per block

__global__ __launch_bounds__(128)
void roi_align_25d_kernel(const float* __restrict__ fea,
                          const float* __restrict__ kp,
                          float* __restrict__ out) {
    const int blk = blockIdx.x;          // 1280 blocks: ROI x channel-group
    const int cgi = blk & 15;            // channel group (4 ch)
    const int n   = blk >> 4;            // ROI index 0..79
    const int b   = n / NKP;

    __shared__ float sW[2][2][WSLOTS];   // [axis][bin][slot], axis0=x(pw), 1=y(ph)
    __shared__ int   sBase[2][2];        // per-axis per-bin base
    __shared__ int   sEnd[2][2];         // per-axis per-bin exclusive end (abs)
    __shared__ int   sG[2];              // adaptive grid per axis

    const int t    = threadIdx.x;
    const int wid  = t >> 5;
    const int lane = t & 31;

    // zero weight slots
    for (int i = t; i < 2 * 2 * WSLOTS; i += 128)
        ((float*)sW)[i] = 0.0f;

    // ---- prologue: 4 threads = (axis, bin) ----
    int   axis = 0, p = 0, g = 0, base = 0;
    float start = 0.f, step = 0.f;
    if (t < 4) {
        axis = t & 1;                    // 0=x, 1=y
        p    = t >> 1;                   // pw (x) or ph (y)
        float coord = kp[n * 3 + axis] * 128.0f;
        float mn = fminf(fmaxf(coord - CROP, 0.0f), 127.0f);
        float mx = fminf(fmaxf(coord + CROP, 0.0f), 127.0f);
        float roi = fmaxf(mx - mn, 1.0f);
        float bin_sz = roi * 0.5f;               // roi / 2
        g = (int)ceilf(bin_sz);                  // 1..16
        step = bin_sz / (float)g;
        start = mn + (float)p * bin_sz;
        float s0 = start + 0.5f * step;
        base = (int)floorf(fmaxf(s0, 0.0f));
        if (base > 127) base = 127;
        sBase[axis][p] = base;
        if (p == 0) sG[axis] = g;
    }
    __syncthreads();
    if (t < 4) {
        const int ubase = sBase[axis][0];        // union base (bin0 base <= bin1 base)
        float* W = sW[axis][p];
        int maxc = base;
        for (int gi = 0; gi < g; gi++) {
            float s = start + ((float)gi + 0.5f) * step;
            if (s < -1.0f || s > 128.0f) continue;   // validity mask
            float c0 = fmaxf(s, 0.0f);
            int l0 = (int)floorf(c0);
            int lo, hi; float fr;
            if (l0 >= 127) { lo = 127; hi = 127; fr = 0.0f; }
            else           { lo = l0;  hi = l0 + 1; fr = c0 - (float)l0; }
            W[lo - ubase] += 1.0f - fr;
            W[hi - ubase] += fr;
            if (hi > maxc) maxc = hi;
        }
        sEnd[axis][p] = maxc + 1;
    }
    __syncthreads();

    const int x0u = sBase[0][0], y0u = sBase[1][0];
    const int nxu = max(sEnd[0][0], sEnd[0][1]) - x0u;   // <= 34
    const int nyu = max(sEnd[1][0], sEnd[1][1]) - y0u;   // <= 34
    const float inv = 1.0f / ((float)(sG[0] * sG[1]));

    const int c  = cgi * WPB + wid;      // channel of this warp
    const int x1 = lane >> 1;            // 0..15
    const int dq = lane & 1;
    const int x2 = x1 + 16;
    const int x3 = x1 + 32;

    // per-lane x-weights for both pw bins (zero-padded slots -> safe reads)
    const float wx0a = sW[0][0][x1], wx1a = sW[0][1][x1];
    const float wx0b = sW[0][0][x2], wx1b = sW[0][1][x2];
    const float wx0c = sW[0][0][x3], wx1c = sW[0][1][x3];

    // clamped addresses for out-of-window lanes (weight 0, L1-hit dup)
    const int xe1 = (x1 < nxu) ? x1 : 0;
    const int xe2 = (x2 < nxu) ? x2 : 0;
    const int xe3 = (x3 < nxu) ? x3 : 0;

    const float4* __restrict__ fp = (const float4*)fea;
    const int rowS  = RW * 2;
    const int base4 = (((b * RC + c) * RH + y0u) * RW + x0u) * 2 + dq;
    const int i1 = base4 + xe1 * 2;
    const int i2 = base4 + xe2 * 2;
    const int i3 = base4 + xe3 * 2;

    const float4 z4 = make_float4(0.f, 0.f, 0.f, 0.f);
    float4 a00 = z4, a01 = z4, a10 = z4, a11 = z4;   // [ph][pw]

    if (nxu > 32) {
        #pragma unroll 4
        for (int y = 0; y < nyu; y++) {
            const float wy0 = sW[1][0][y];
            const float wy1 = sW[1][1][y];
            const float4 v1 = fp[i1 + y * rowS];
            const float4 v2 = fp[i2 + y * rowS];
            const float4 v3 = fp[i3 + y * rowS];
            float4 t0, t1;
            t0.x = wx0a*v1.x + wx0b*v2.x + wx0c*v3.x;
            t0.y = wx0a*v1.y + wx0b*v2.y + wx0c*v3.y;
            t0.z = wx0a*v1.z + wx0b*v2.z + wx0c*v3.z;
            t0.w = wx0a*v1.w + wx0b*v2.w + wx0c*v3.w;
            t1.x = wx1a*v1.x + wx1b*v2.x + wx1c*v3.x;
            t1.y = wx1a*v1.y + wx1b*v2.y + wx1c*v3.y;
            t1.z = wx1a*v1.z + wx1b*v2.z + wx1c*v3.z;
            t1.w = wx1a*v1.w + wx1b*v2.w + wx1c*v3.w;
            a00.x += wy0*t0.x;  a00.y += wy0*t0.y;  a00.z += wy0*t0.z;  a00.w += wy0*t0.w;
            a01.x += wy0*t1.x;  a01.y += wy0*t1.y;  a01.z += wy0*t1.z;  a01.w += wy0*t1.w;
            a10.x += wy1*t0.x;  a10.y += wy1*t0.y;  a10.z += wy1*t0.z;  a10.w += wy1*t0.w;
            a11.x += wy1*t1.x;  a11.y += wy1*t1.y;  a11.z += wy1*t1.z;  a11.w += wy1*t1.w;
        }
    } else {
        #pragma unroll 4
        for (int y = 0; y < nyu; y++) {
            const float wy0 = sW[1][0][y];
            const float wy1 = sW[1][1][y];
            const float4 v1 = fp[i1 + y * rowS];
            const float4 v2 = fp[i2 + y * rowS];
            float4 t0, t1;
            t0.x = wx0a*v1.x + wx0b*v2.x;
            t0.y = wx0a*v1.y + wx0b*v2.y;
            t0.z = wx0a*v1.z + wx0b*v2.z;
            t0.w = wx0a*v1.w + wx0b*v2.w;
            t1.x = wx1a*v1.x + wx1b*v2.x;
            t1.y = wx1a*v1.y + wx1b*v2.y;
            t1.z = wx1a*v1.z + wx1b*v2.z;
            t1.w = wx1a*v1.w + wx1b*v2.w;
            a00.x += wy0*t0.x;  a00.y += wy0*t0.y;  a00.z += wy0*t0.z;  a00.w += wy0*t0.w;
            a01.x += wy0*t1.x;  a01.y += wy0*t1.y;  a01.z += wy0*t1.z;  a01.w += wy0*t1.w;
            a10.x += wy1*t0.x;  a10.y += wy1*t0.y;  a10.z += wy1*t0.z;  a10.w += wy1*t0.w;
            a11.x += wy1*t1.x;  a11.y += wy1*t1.y;  a11.z += wy1*t1.z;  a11.w += wy1*t1.w;
        }
    }

    // Reduce over x (lane bits 1..4); every lane ends with totals for its dq.
    #pragma unroll
    for (int m = 2; m <= 16; m <<= 1) {
        a00.x += __shfl_xor_sync(0xffffffffu, a00.x, m);
        a00.y += __shfl_xor_sync(0xffffffffu, a00.y, m);
        a00.z += __shfl_xor_sync(0xffffffffu, a00.z, m);
        a00.w += __shfl_xor_sync(0xffffffffu, a00.w, m);
        a01.x += __shfl_xor_sync(0xffffffffu, a01.x, m);
        a01.y += __shfl_xor_sync(0xffffffffu, a01.y, m);
        a01.z += __shfl_xor_sync(0xffffffffu, a01.z, m);
        a01.w += __shfl_xor_sync(0xffffffffu, a01.w, m);
        a10.x += __shfl_xor_sync(0xffffffffu, a10.x, m);
        a10.y += __shfl_xor_sync(0xffffffffu, a10.y, m);
        a10.z += __shfl_xor_sync(0xffffffffu, a10.z, m);
        a10.w += __shfl_xor_sync(0xffffffffu, a10.w, m);
        a11.x += __shfl_xor_sync(0xffffffffu, a11.x, m);
        a11.y += __shfl_xor_sync(0xffffffffu, a11.y, m);
        a11.z += __shfl_xor_sync(0xffffffffu, a11.z, m);
        a11.w += __shfl_xor_sync(0xffffffffu, a11.w, m);
    }

    if (lane < 2) {
        // out: (NROI, C, 2, 2, 8) -> float4 index (n*C+c)*8 + (ph*2+pw)*2 + dq
        float4* __restrict__ op = (float4*)out;
        const int cb = (n * RC + c) * 8 + dq;
        float4 s;
        s.x = a00.x*inv; s.y = a00.y*inv; s.z = a00.z*inv; s.w = a00.w*inv;
        op[cb + 0] = s;
        s.x = a01.x*inv; s.y = a01.y*inv; s.z = a01.z*inv; s.w = a01.w*inv;
        op[cb + 2] = s;
        s.x = a10.x*inv; s.y = a10.y*inv; s.z = a10.z*inv; s.w = a10.w*inv;
        op[cb + 4] = s;
        s.x = a11.x*inv; s.y = a11.y*inv; s.z = a11.z*inv; s.w = a11.w*inv;
        op[cb + 6] = s;
    }
}

extern "C" void kernel_launch(void* const* d_in, const int* in_sizes, int n_in,
                              void* d_out, int out_size) {
    const float* fea = (const float*)d_in[0];
    const float* kp  = (const float*)d_in[1];
    float* out = (float*)d_out;
    (void)in_sizes; (void)n_in; (void)out_size;

    dim3 grid(NROI * 16);      // 1280 blocks: ROI x 4-channel group
    dim3 block(32 * WPB);      // 4 warps, each one channel, all 4 bins fused
    roi_align_25d_kernel<<<grid, block>>>(fea, kp, out);
}

// round 14
// speedup vs baseline: 1.2143x; 1.1020x over previous
#include <cuda_runtime.h>
#include <cuda_bf16.h>

// ROI align 2.5D — separable-weight formulation.
// fea: (B=16, C=64, H=128, W=128, D=8) f32, contiguous.
// keypoints: (16, 5, 3) f32.
// out: (16, 5, 64, 2, 2, 8) f32.
//
// Per (ROI, bin): out[c,d] = (1/(gh*gw)) * sum_y Wy[y] * sum_x Wx[x] * fea[b,c,y,x,d]
//
// R14 = R6 (best: warp-per-channel, 512B spans, dup-clamped tail) with hot
// loads carrying an L2::evict_last cache policy (createpolicy + cache_hint
// form — inline .L2::evict_last on v4.f32 is rejected by this ptxas). The
// ~150MB ROI footprint is near L2 capacity (126MB); high retention priority
// keeps it L2-resident ACROSS graph replays, collapsing steady-state DRAM.

#define RB  16
#define RC  64
#define RH  128
#define RW  128
#define RD  8
#define NKP 5
#define NROI (RB * NKP)          // 80
#define CROP 16.0f               // H * 1/8
#define WSLOTS 32                // padded so Wx[x+16] (x<16) is always in-bounds
#define WPB 8                    // warps (channels) per block

__device__ __forceinline__ unsigned long long mk_policy_el() {
    unsigned long long pol;
    asm("createpolicy.fractional.L2::evict_last.b64 %0, 1.0;" : "=l"(pol));
    return pol;
}

__device__ __forceinline__ float4 ldg_el(const float4* p, unsigned long long pol) {
    float4 v;
    asm volatile("ld.global.nc.L2::cache_hint.v4.f32 {%0,%1,%2,%3}, [%4], %5;"
                 : "=f"(v.x), "=f"(v.y), "=f"(v.z), "=f"(v.w)
                 : "l"(p), "l"(pol));
    return v;
}

__global__ __launch_bounds__(256)
void roi_align_25d_kernel(const float* __restrict__ fea,
                          const float* __restrict__ kp,
                          float* __restrict__ out) {
    const int blk = blockIdx.x;          // 2560 blocks: ROI x bin x cg
    const int cg  = blk & 7;             // channel group (8 ch)
    const int bin = (blk >> 3) & 3;      // ph*2 + pw
    const int n   = blk >> 5;            // ROI index 0..79
    const int ph  = bin >> 1;
    const int pw  = bin & 1;
    const int b   = n / NKP;

    __shared__ float Wx[WSLOTS], Wy[WSLOTS];
    __shared__ int   sBase[2];   // [0]=x0, [1]=y0
    __shared__ int   sCnt[2];    // [0]=nx, [1]=ny
    __shared__ int   sG[2];      // [0]=gw, [1]=gh

    const int t    = threadIdx.x;
    const int wid  = t >> 5;
    const int lane = t & 31;

    if (t < 2) {
        // t==0 -> x axis (uses pw), t==1 -> y axis (uses ph)
        float coord = kp[n * 3 + t] * 128.0f;
        float mn = fminf(fmaxf(coord - CROP, 0.0f), 127.0f);
        float mx = fminf(fmaxf(coord + CROP, 0.0f), 127.0f);
        float roi = fmaxf(mx - mn, 1.0f);
        float bin_sz = roi * 0.5f;                 // roi / P (P=2)
        int   g = (int)ceilf(bin_sz);              // ceil(roi/2), 1..16
        float step = bin_sz / (float)g;
        int   p = (t == 0) ? pw : ph;
        float start = mn + (float)p * bin_sz;

        float* Wp = (t == 0) ? Wx : Wy;
        #pragma unroll
        for (int i = 0; i < WSLOTS; i++) Wp[i] = 0.0f;

        // first sample defines the base index (samples are monotone in g)
        float s0 = start + 0.5f * step;
        int base = (int)floorf(fmaxf(s0, 0.0f));
        if (base > 127) base = 127;
        int maxc = base;

        for (int gi = 0; gi < g; gi++) {
            float s = start + ((float)gi + 0.5f) * step;
            if (s < -1.0f || s > 128.0f) continue;     // validity mask
            float c0 = fmaxf(s, 0.0f);
            int l0 = (int)floorf(c0);
            int lo, hi; float fr;
            if (l0 >= 127) { lo = 127; hi = 127; fr = 0.0f; }
            else           { lo = l0;  hi = l0 + 1; fr = c0 - (float)l0; }
            Wp[lo - base] += 1.0f - fr;
            Wp[hi - base] += fr;
            if (hi > maxc) maxc = hi;
        }
        sBase[t] = base;
        sCnt[t]  = maxc - base + 1;
        sG[t]    = g;
    }
    __syncthreads();

    const int x0 = sBase[0], nx = sCnt[0];
    const int y0 = sBase[1], ny = sCnt[1];
    const float inv = 1.0f / ((float)sG[0] * (float)sG[1]);

    const int c  = cg * WPB + wid;       // channel of this warp
    const int x  = lane >> 1;            // x-pixel within window, 0..15
    const int dq = lane & 1;             // which float4 of the 8-float depth

    const float4* __restrict__ fp = (const float4*)fea;
    const unsigned long long pol = mk_policy_el();

    // Per-lane weights; clamp OOW lanes to x=0 (weight is 0, load is L1 dup).
    const float wx1 = Wx[x];
    const int   xe1 = (x < nx) ? x : 0;
    const float wx2 = Wx[x + 16];                 // zero-padded -> safe
    const int   xe2 = (x + 16 < nx) ? x + 16 : 0;

    // float4 index: (((b*C + c)*H + y)*W + x)*2 + dq   (max ~33.5M, fits int)
    const int rowStride = RW * 2;
    int idx1 = (((b * RC + c) * RH + y0) * RW + x0 + xe1) * 2 + dq;
    int idx2 = (((b * RC + c) * RH + y0) * RW + x0 + xe2) * 2 + dq;

    float4 acc1 = make_float4(0.f, 0.f, 0.f, 0.f);
    float4 acc2 = make_float4(0.f, 0.f, 0.f, 0.f);

    if (nx <= 16) {
        #pragma unroll 4
        for (int iy = 0; iy < ny; iy++) {
            const float wy = Wy[iy];
            const float4 v = ldg_el(fp + idx1 + iy * rowStride, pol);
            acc1.x += wy * v.x;  acc1.y += wy * v.y;
            acc1.z += wy * v.z;  acc1.w += wy * v.w;
        }
    } else {
        #pragma unroll 4
        for (int iy = 0; iy < ny; iy++) {
            const float wy = Wy[iy];
            const float4 v1 = ldg_el(fp + idx1 + iy * rowStride, pol);
            const float4 v2 = ldg_el(fp + idx2 + iy * rowStride, pol);
            acc1.x += wy * v1.x;  acc1.y += wy * v1.y;
            acc1.z += wy * v1.z;  acc1.w += wy * v1.w;
            acc2.x += wy * v2.x;  acc2.y += wy * v2.y;
            acc2.z += wy * v2.z;  acc2.w += wy * v2.w;
        }
    }

    float4 s;
    s.x = wx1 * acc1.x + wx2 * acc2.x;
    s.y = wx1 * acc1.y + wx2 * acc2.y;
    s.z = wx1 * acc1.z + wx2 * acc2.z;
    s.w = wx1 * acc1.w + wx2 * acc2.w;

    // Reduce over x (lane bits 1..4), keeping dq pairs separate.
    #pragma unroll
    for (int m = 2; m <= 16; m <<= 1) {
        s.x += __shfl_xor_sync(0xffffffffu, s.x, m);
        s.y += __shfl_xor_sync(0xffffffffu, s.y, m);
        s.z += __shfl_xor_sync(0xffffffffu, s.z, m);
        s.w += __shfl_xor_sync(0xffffffffu, s.w, m);
    }

    if (lane < 2) {
        s.x *= inv; s.y *= inv; s.z *= inv; s.w *= inv;
        // out: (NROI, C, 2, 2, 8) -> float4 index (((n*C+c)*2+ph)*2+pw)*2+dq
        float4* __restrict__ op = (float4*)out;
        op[(((n * RC + c) * 2 + ph) * 2 + pw) * 2 + dq] = s;
    }
}

extern "C" void kernel_launch(void* const* d_in, const int* in_sizes, int n_in,
                              void* d_out, int out_size) {
    const float* fea = (const float*)d_in[0];
    const float* kp  = (const float*)d_in[1];
    float* out = (float*)d_out;
    (void)in_sizes; (void)n_in; (void)out_size;

    dim3 grid(NROI * 4 * (RC / WPB));   // 2560 blocks: ROI x bin x channel-group
    dim3 block(32 * WPB);               // 8 warps = 8 channels
    roi_align_25d_kernel<<<grid, block>>>(fea, kp, out);
}

// round 15
// speedup vs baseline: 1.2947x; 1.0662x over previous
#include <cuda_runtime.h>
#include <cuda_bf16.h>

// ROI align 2.5D — separable-weight formulation.
// fea: (B=16, C=64, H=128, W=128, D=8) f32, contiguous.
// keypoints: (16, 5, 3) f32.
// out: (16, 5, 64, 2, 2, 8) f32.
//
// Per (ROI, bin): out[c,d] = (1/(gh*gw)) * sum_y Wy[y] * sum_x Wx[x] * fea[b,c,y,x,d]
//
// R15 = R6 (warp-per-channel, 512B spans) with the inner loop split into an
// explicit 8-deep LOAD BATCH into registers followed by consumption: 8
// independent LDG.128 in flight per thread (vs ~4), doubling chip-wide
// outstanding bytes (~1MB -> ~2MB). Little's law: DRAM demand was the
// binding constraint pinning HBM at ~50% across 8 prior variants.

#define RB  16
#define RC  64
#define RH  128
#define RW  128
#define RD  8
#define NKP 5
#define NROI (RB * NKP)          // 80
#define CROP 16.0f               // H * 1/8
#define WSLOTS 32                // zero-padded: Wy[iy>=ny]=0, Wx[x+16]=0 safe
#define WPB 8                    // warps (channels) per block

__global__ __launch_bounds__(256, 4)
void roi_align_25d_kernel(const float* __restrict__ fea,
                          const float* __restrict__ kp,
                          float* __restrict__ out) {
    const int blk = blockIdx.x;          // 2560 blocks: ROI x bin x cg
    const int cg  = blk & 7;             // channel group (8 ch)
    const int bin = (blk >> 3) & 3;      // ph*2 + pw
    const int n   = blk >> 5;            // ROI index 0..79
    const int ph  = bin >> 1;
    const int pw  = bin & 1;
    const int b   = n / NKP;

    __shared__ float Wx[WSLOTS], Wy[WSLOTS];
    __shared__ int   sBase[2];   // [0]=x0, [1]=y0
    __shared__ int   sCnt[2];    // [0]=nx, [1]=ny
    __shared__ int   sG[2];      // [0]=gw, [1]=gh

    const int t    = threadIdx.x;
    const int wid  = t >> 5;
    const int lane = t & 31;

    if (t < 2) {
        // t==0 -> x axis (uses pw), t==1 -> y axis (uses ph)
        float coord = kp[n * 3 + t] * 128.0f;
        float mn = fminf(fmaxf(coord - CROP, 0.0f), 127.0f);
        float mx = fminf(fmaxf(coord + CROP, 0.0f), 127.0f);
        float roi = fmaxf(mx - mn, 1.0f);
        float bin_sz = roi * 0.5f;                 // roi / P (P=2)
        int   g = (int)ceilf(bin_sz);              // ceil(roi/2), 1..16
        float step = bin_sz / (float)g;
        int   p = (t == 0) ? pw : ph;
        float start = mn + (float)p * bin_sz;

        float* Wp = (t == 0) ? Wx : Wy;
        #pragma unroll
        for (int i = 0; i < WSLOTS; i++) Wp[i] = 0.0f;

        // first sample defines the base index (samples are monotone in g)
        float s0 = start + 0.5f * step;
        int base = (int)floorf(fmaxf(s0, 0.0f));
        if (base > 127) base = 127;
        int maxc = base;

        for (int gi = 0; gi < g; gi++) {
            float s = start + ((float)gi + 0.5f) * step;
            if (s < -1.0f || s > 128.0f) continue;     // validity mask
            float c0 = fmaxf(s, 0.0f);
            int l0 = (int)floorf(c0);
            int lo, hi; float fr;
            if (l0 >= 127) { lo = 127; hi = 127; fr = 0.0f; }
            else           { lo = l0;  hi = l0 + 1; fr = c0 - (float)l0; }
            Wp[lo - base] += 1.0f - fr;
            Wp[hi - base] += fr;
            if (hi > maxc) maxc = hi;
        }
        sBase[t] = base;
        sCnt[t]  = maxc - base + 1;
        sG[t]    = g;
    }
    __syncthreads();

    const int x0 = sBase[0], nx = sCnt[0];
    const int y0 = sBase[1], ny = sCnt[1];
    const float inv = 1.0f / ((float)sG[0] * (float)sG[1]);

    const int c  = cg * WPB + wid;       // channel of this warp
    const int x  = lane >> 1;            // x-pixel within window, 0..15
    const int dq = lane & 1;             // which float4 of the 8-float depth

    const float4* __restrict__ fp = (const float4*)fea;

    // Per-lane weights; clamp OOW lanes to x=0 (weight is 0, load is L1 dup).
    const float wx1 = Wx[x];
    const int   xe1 = (x < nx) ? x : 0;
    const float wx2 = Wx[x + 16];                 // zero-padded -> safe
    const int   xe2 = (x + 16 < nx) ? x + 16 : 0;

    // float4 index: (((b*C + c)*H + y)*W + x)*2 + dq   (max ~33.5M, fits int)
    const int rowStride = RW * 2;
    const int idx1 = (((b * RC + c) * RH + y0) * RW + x0 + xe1) * 2 + dq;
    const int idx2 = (((b * RC + c) * RH + y0) * RW + x0 + xe2) * 2 + dq;

    float4 acc1 = make_float4(0.f, 0.f, 0.f, 0.f);
    float4 acc2 = make_float4(0.f, 0.f, 0.f, 0.f);

    const int nyM1 = ny - 1;

    if (nx <= 16) {
        // 8-row load batches: 8 independent LDG.128 in flight per thread.
        // Rows past ny are clamped dups (L1 hit); Wy is zero there.
        const int nyPad = (ny + 7) & ~7;            // <= 24 < WSLOTS
        for (int iy0 = 0; iy0 < nyPad; iy0 += 8) {
            float4 vb[8];
            #pragma unroll
            for (int j = 0; j < 8; j++) {
                const int iyc = min(iy0 + j, nyM1);
                vb[j] = fp[idx1 + iyc * rowStride];
            }
            #pragma unroll
            for (int j = 0; j < 8; j++) {
                const float wy = Wy[iy0 + j];
                acc1.x += wy * vb[j].x;  acc1.y += wy * vb[j].y;
                acc1.z += wy * vb[j].z;  acc1.w += wy * vb[j].w;
            }
        }
    } else {
        // 4-row batches x 2 spans = 8 loads in flight.
        const int nyPad = (ny + 3) & ~3;            // <= 20 < WSLOTS
        for (int iy0 = 0; iy0 < nyPad; iy0 += 4) {
            float4 va[4], vb[4];
            #pragma unroll
            for (int j = 0; j < 4; j++) {
                const int iyc = min(iy0 + j, nyM1);
                va[j] = fp[idx1 + iyc * rowStride];
                vb[j] = fp[idx2 + iyc * rowStride];
            }
            #pragma unroll
            for (int j = 0; j < 4; j++) {
                const float wy = Wy[iy0 + j];
                acc1.x += wy * va[j].x;  acc1.y += wy * va[j].y;
                acc1.z += wy * va[j].z;  acc1.w += wy * va[j].w;
                acc2.x += wy * vb[j].x;  acc2.y += wy * vb[j].y;
                acc2.z += wy * vb[j].z;  acc2.w += wy * vb[j].w;
            }
        }
    }

    float4 s;
    s.x = wx1 * acc1.x + wx2 * acc2.x;
    s.y = wx1 * acc1.y + wx2 * acc2.y;
    s.z = wx1 * acc1.z + wx2 * acc2.z;
    s.w = wx1 * acc1.w + wx2 * acc2.w;

    // Reduce over x (lane bits 1..4), keeping dq pairs separate.
    #pragma unroll
    for (int m = 2; m <= 16; m <<= 1) {
        s.x += __shfl_xor_sync(0xffffffffu, s.x, m);
        s.y += __shfl_xor_sync(0xffffffffu, s.y, m);
        s.z += __shfl_xor_sync(0xffffffffu, s.z, m);
        s.w += __shfl_xor_sync(0xffffffffu, s.w, m);
    }

    if (lane < 2) {
        s.x *= inv; s.y *= inv; s.z *= inv; s.w *= inv;
        // out: (NROI, C, 2, 2, 8) -> float4 index (((n*C+c)*2+ph)*2+pw)*2+dq
        float4* __restrict__ op = (float4*)out;
        op[(((n * RC + c) * 2 + ph) * 2 + pw) * 2 + dq] = s;
    }
}

extern "C" void kernel_launch(void* const* d_in, const int* in_sizes, int n_in,
                              void* d_out, int out_size) {
    const float* fea = (const float*)d_in[0];
    const float* kp  = (const float*)d_in[1];
    float* out = (float*)d_out;
    (void)in_sizes; (void)n_in; (void)out_size;

    dim3 grid(NROI * 4 * (RC / WPB));   // 2560 blocks: ROI x bin x channel-group
    dim3 block(32 * WPB);               // 8 warps = 8 channels
    roi_align_25d_kernel<<<grid, block>>>(fea, kp, out);
}